// round 17
// baseline (speedup 1.0000x reference)
#include <cuda_runtime.h>
#include <cuda_fp16.h>
#include <mma.h>
#include <cstdint>

using namespace nvcuda;

#define N_NODES 100000
#define N_EDGES 1600000
#define FIN 128
#define FH 64
#define FOUT 40
#define MAXD 64    // ELL cap; in-deg ~ Poisson(16), P(any node >= 64) < 1e-15

#define GEMM1_BLOCKS ((N_NODES + 63) / 64)          // 1563
#define BUCKET_BLOCKS ((N_EDGES + 255) / 256)       // 6250

// ---------------- scratch (device globals; no allocs allowed) ----------------
__device__ __align__(16) __half2 g_h1h[(size_t)N_NODES * 32];  // x@W1 (UNscaled), fp16
__device__ __align__(16) __half2 g_h2ph[(size_t)N_NODES * 20]; // (a1'@W2)*inv, fp16
__device__ __align__(16) __half  g_a1h[(size_t)N_NODES * FH];  // dropout(relu(a1+b1)), fp16
__device__ __align__(16) __half  g_w1h[FIN * FH];              // fp16 W1
__device__ int   g_srcs[(size_t)N_NODES * MAXD];               // ELL in-edge source lists
__device__ int   g_deg[N_NODES];
__device__ float g_inv[N_NODES];
__device__ int   g_is64;

struct alignas(16) H8 { __half2 a, b, c, d; };

// ---------------- helpers ----------------
__device__ __forceinline__ int load_idx(const void* ei, int half, int e) {
    if (g_is64) return (int)((const long long*)ei)[(size_t)half * N_EDGES + e];
    return ((const int*)ei)[(size_t)half * N_EDGES + e];
}

// Threefry-2x32, 20 rounds (JAX rotation schedule) — verified bit-exact vs ref
__device__ __forceinline__ uint2 threefry2x32(uint32_t k0, uint32_t k1,
                                              uint32_t x0, uint32_t x1) {
    uint32_t ks2 = 0x1BD11BDAu ^ k0 ^ k1;
    x0 += k0; x1 += k1;
#define TF_R(r) { x0 += x1; x1 = __funnelshift_l(x1, x1, r); x1 ^= x0; }
    TF_R(13) TF_R(15) TF_R(26) TF_R(6)
    x0 += k1;  x1 += ks2 + 1u;
    TF_R(17) TF_R(29) TF_R(16) TF_R(24)
    x0 += ks2; x1 += k0 + 2u;
    TF_R(13) TF_R(15) TF_R(26) TF_R(6)
    x0 += k0;  x1 += k1 + 3u;
    TF_R(17) TF_R(29) TF_R(16) TF_R(24)
    x0 += k1;  x1 += ks2 + 4u;
    TF_R(13) TF_R(15) TF_R(26) TF_R(6)
    x0 += ks2; x1 += k0 + 5u;
#undef TF_R
    return make_uint2(x0, x1);
}

__device__ __forceinline__ bool keep_mask(uint32_t i) {
    uint2 o = threefry2x32(0u, 42u, 0u, i);
    uint32_t bits = o.x ^ o.y;
    float u = __uint_as_float((bits >> 9) | 0x3f800000u) - 1.0f;
    return u < 0.5f;
}

__device__ __forceinline__ float4 h4_to_f4(uint2 raw) {
    float2 a = __half22float2(*reinterpret_cast<__half2*>(&raw.x));
    float2 b = __half22float2(*reinterpret_cast<__half2*>(&raw.y));
    return make_float4(a.x, a.y, b.x, b.y);
}

// ---------------- init: zero deg + detect width + quantize W1 ----------------
__global__ void k_init(const long long* ei, const float* __restrict__ W1) {
    __shared__ int s_ok;
    int i = blockIdx.x * 256 + threadIdx.x;
    if (i < N_NODES) g_deg[i] = 0;
    if (i < FIN * FH / 4) {
        float4 v = ((const float4*)W1)[i];
        __half2 h0 = __floats2half2_rn(v.x, v.y);
        __half2 h1 = __floats2half2_rn(v.z, v.w);
        ((uint2*)g_w1h)[i] = make_uint2(*(uint32_t*)&h0, *(uint32_t*)&h1);
    }
    if (blockIdx.x == 0) {
        if (threadIdx.x == 0) s_ok = 1;
        __syncthreads();
        if (threadIdx.x < 128) {
            long long v = ei[threadIdx.x];
            if (v < 0 || v >= N_NODES) atomicAnd(&s_ok, 0);
        }
        __syncthreads();
        if (threadIdx.x == 0) g_is64 = s_ok;
    }
}

// ---------------- fused: gemm1 (blocks 0..GEMM1) || bucket (rest) ----------------
// gemm1: h1h = fp16( x @ W1 ), UNscaled (inv applied in agg1)
#define GX_LD 136   // halfs
#define GW_LD 72    // halfs
__global__ void __launch_bounds__(256) k_fused(const float* __restrict__ x,
                                               const void* ei) {
    __shared__ __align__(16) __half sX[64 * GX_LD];   // 17408 B; reused as 64x64 f32 C
    __shared__ __align__(16) __half sW[FIN * GW_LD];  // 18432 B, [k][n]

    int tid = threadIdx.x;

    if (blockIdx.x >= GEMM1_BLOCKS) {
        // ---- bucket branch ----
        int e = (blockIdx.x - GEMM1_BLOCKS) * 256 + tid;
        if (e < N_EDGES) {
            int s = load_idx(ei, 0, e);
            int d = load_idx(ei, 1, e);
            int pos = atomicAdd(&g_deg[d], 1);
            if (pos < MAXD) g_srcs[(size_t)d * MAXD + pos] = s;
        }
        return;
    }

    // ---- gemm1 branch ----
    int wid = tid >> 5;
    int row0 = blockIdx.x * 64;

    for (int idx = tid; idx < FIN * FH / 8; idx += 256) {
        uint4 v = ((const uint4*)g_w1h)[idx];
        int k = idx >> 3;
        int c = idx & 7;
        *(uint4*)(sW + k * GW_LD + c * 8) = v;
    }
    for (int idx = tid; idx < 64 * FIN / 4; idx += 256) {
        int flat = idx * 4;
        int r = flat >> 7;
        int c = flat & 127;
        float4 v = make_float4(0.f, 0.f, 0.f, 0.f);
        int grow = row0 + r;
        if (grow < N_NODES)
            v = *(const float4*)(x + (size_t)grow * FIN + c);
        __half2 h0 = __floats2half2_rn(v.x, v.y);
        __half2 h1 = __floats2half2_rn(v.z, v.w);
        *(uint2*)(sX + r * GX_LD + c) = make_uint2(*(uint32_t*)&h0, *(uint32_t*)&h1);
    }
    __syncthreads();

    int rs = wid & 3;
    int ct = wid >> 2;
    wmma::fragment<wmma::accumulator, 16, 16, 16, float> fc[2];
#pragma unroll
    for (int nt = 0; nt < 2; nt++) wmma::fill_fragment(fc[nt], 0.0f);

#pragma unroll
    for (int k = 0; k < FIN; k += 16) {
        wmma::fragment<wmma::matrix_a, 16, 16, 16, __half, wmma::row_major> fa;
        wmma::load_matrix_sync(fa, sX + (rs * 16) * GX_LD + k, GX_LD);
#pragma unroll
        for (int nt = 0; nt < 2; nt++) {
            wmma::fragment<wmma::matrix_b, 16, 16, 16, __half, wmma::row_major> fb;
            wmma::load_matrix_sync(fb, sW + k * GW_LD + ct * 32 + nt * 16, GW_LD);
            wmma::mma_sync(fc[nt], fa, fb, fc[nt]);
        }
    }

    __syncthreads();
    float* sC = (float*)sX;                // 64 x 64, ld 64
#pragma unroll
    for (int nt = 0; nt < 2; nt++)
        wmma::store_matrix_sync(sC + (rs * 16) * 64 + ct * 32 + nt * 16, fc[nt], 64,
                                wmma::mem_row_major);
    __syncthreads();

    // epilogue: pack half2 (no scaling) -> g_h1h
    {
        int r = tid >> 2;
        int qt = tid & 3;
        int grow = row0 + r;
        if (grow < N_NODES) {
            const float* src = sC + r * 64 + qt * 16;
            H8* dst = (H8*)(g_h1h + (size_t)grow * 32) + qt * 2;
#pragma unroll
            for (int b = 0; b < 2; b++) {
                H8 pk;
                pk.a = __floats2half2_rn(src[b * 8 + 0], src[b * 8 + 1]);
                pk.b = __floats2half2_rn(src[b * 8 + 2], src[b * 8 + 3]);
                pk.c = __floats2half2_rn(src[b * 8 + 4], src[b * 8 + 5]);
                pk.d = __floats2half2_rn(src[b * 8 + 6], src[b * 8 + 7]);
                dst[b] = pk;
            }
        }
    }
}

__global__ void k_inv() {
    int i = blockIdx.x * 256 + threadIdx.x;
    if (i < N_NODES) g_inv[i] = rsqrtf((float)g_deg[i] + 1.0f);
}

// gather-aggregate layer1 + fused transform:
// a1 = inv[d]*( Σ inv[s]·h1[s] + inv[d]·h1[d] );  a1h = fp16(dropout(relu(a1+b1)))
// 16 lanes/dst, 4 halves each; 8-wide load batching
__global__ void __launch_bounds__(256) k_agg1(const float* __restrict__ b1) {
    long long t = (long long)blockIdx.x * 256 + threadIdx.x;
    int d = (int)(t >> 4);
    if (d >= N_NODES) return;
    int q = (int)(t & 15);
    int cnt = g_deg[d];
    if (cnt > MAXD) cnt = MAXD;
    const int* sp = g_srcs + (size_t)d * MAXD;
    float wd = g_inv[d];

    float4 sf = h4_to_f4(((const uint2*)(g_h1h + (size_t)d * 32))[q]);
    float4 acc = make_float4(sf.x * wd, sf.y * wd, sf.z * wd, sf.w * wd);   // self

    int j = 0;
    for (; j + 8 <= cnt; j += 8) {
        int   si[8];
        float wi[8];
        uint2 ri[8];
#pragma unroll
        for (int u = 0; u < 8; u++) si[u] = __ldg(&sp[j + u]);
#pragma unroll
        for (int u = 0; u < 8; u++) {
            wi[u] = __ldg(&g_inv[si[u]]);
            ri[u] = __ldg((const uint2*)(g_h1h + (size_t)si[u] * 32) + q);
        }
#pragma unroll
        for (int u = 0; u < 8; u++) {
            float4 v = h4_to_f4(ri[u]);
            acc.x = fmaf(v.x, wi[u], acc.x);
            acc.y = fmaf(v.y, wi[u], acc.y);
            acc.z = fmaf(v.z, wi[u], acc.z);
            acc.w = fmaf(v.w, wi[u], acc.w);
        }
    }
    for (; j < cnt; j++) {
        int s = __ldg(&sp[j]);
        float ws = __ldg(&g_inv[s]);
        float4 v = h4_to_f4(__ldg((const uint2*)(g_h1h + (size_t)s * 32) + q));
        acc.x = fmaf(v.x, ws, acc.x);
        acc.y = fmaf(v.y, ws, acc.y);
        acc.z = fmaf(v.z, ws, acc.z);
        acc.w = fmaf(v.w, ws, acc.w);
    }

    int c0 = q * 4;
    uint32_t ib = (uint32_t)d * FH + c0;
    float t0 = fmaxf(acc.x * wd + __ldg(&b1[c0 + 0]), 0.0f);
    float t1 = fmaxf(acc.y * wd + __ldg(&b1[c0 + 1]), 0.0f);
    float t2 = fmaxf(acc.z * wd + __ldg(&b1[c0 + 2]), 0.0f);
    float t3 = fmaxf(acc.w * wd + __ldg(&b1[c0 + 3]), 0.0f);
    t0 = keep_mask(ib + 0) ? t0 * 2.0f : 0.0f;
    t1 = keep_mask(ib + 1) ? t1 * 2.0f : 0.0f;
    t2 = keep_mask(ib + 2) ? t2 * 2.0f : 0.0f;
    t3 = keep_mask(ib + 3) ? t3 * 2.0f : 0.0f;
    __half2 h0 = __floats2half2_rn(t0, t1);
    __half2 h1 = __floats2half2_rn(t2, t3);
    *(uint2*)(g_a1h + (size_t)d * FH + c0) = make_uint2(*(uint32_t*)&h0, *(uint32_t*)&h1);
}

// ---------------- gemm2: wmma fp16, 128 rows/block; A pre-transformed in agg1 ----
#define A2_LD 72    // halfs
#define W2_LD 48    // halfs
#define C2_LD 48    // floats
__global__ void __launch_bounds__(256) k_gemm2(const float* __restrict__ W2) {
    __shared__ __align__(16) char smem[24576];
    __half* sA  = (__half*)smem;                      // [128][A2_LD]
    __half* sW2 = (__half*)(smem + 128 * A2_LD * 2);  // [64][W2_LD]
    float*  sC  = (float*)smem;                       // [128][C2_LD]

    int tid = threadIdx.x;
    int wid = tid >> 5;
    int row0 = blockIdx.x * 128;

    for (int idx = tid; idx < FH * 48 / 4; idx += 256) {
        int flat = idx * 4;
        int k = flat / 48;
        int n = flat % 48;
        float4 v = make_float4(0.f, 0.f, 0.f, 0.f);
        if (n + 3 < FOUT)
            v = *(const float4*)(W2 + k * FOUT + n);
        __half2 h0 = __floats2half2_rn(v.x, v.y);
        __half2 h1 = __floats2half2_rn(v.z, v.w);
        *(uint2*)(sW2 + k * W2_LD + n) = make_uint2(*(uint32_t*)&h0, *(uint32_t*)&h1);
    }
    for (int idx = tid; idx < 128 * FH / 8; idx += 256) {
        int r = idx >> 3;
        int c = (idx & 7) * 8;
        int grow = row0 + r;
        uint4 v = make_uint4(0u, 0u, 0u, 0u);
        if (grow < N_NODES)
            v = *(const uint4*)(g_a1h + (size_t)grow * FH + c);
        *(uint4*)(sA + r * A2_LD + c) = v;
    }
    __syncthreads();

    wmma::fragment<wmma::accumulator, 16, 16, 16, float> fc[3];
#pragma unroll
    for (int nt = 0; nt < 3; nt++) wmma::fill_fragment(fc[nt], 0.0f);

#pragma unroll
    for (int k = 0; k < FH; k += 16) {
        wmma::fragment<wmma::matrix_a, 16, 16, 16, __half, wmma::row_major> fa;
        wmma::load_matrix_sync(fa, sA + (wid * 16) * A2_LD + k, A2_LD);
#pragma unroll
        for (int nt = 0; nt < 3; nt++) {
            wmma::fragment<wmma::matrix_b, 16, 16, 16, __half, wmma::row_major> fb;
            wmma::load_matrix_sync(fb, sW2 + k * W2_LD + nt * 16, W2_LD);
            wmma::mma_sync(fc[nt], fa, fb, fc[nt]);
        }
    }

    __syncthreads();
#pragma unroll
    for (int nt = 0; nt < 3; nt++)
        wmma::store_matrix_sync(sC + (wid * 16) * C2_LD + nt * 16, fc[nt], C2_LD,
                                wmma::mem_row_major);
    __syncthreads();

    {
        int r = tid >> 1;
        int hh = tid & 1;
        int grow = row0 + r;
        if (grow < N_NODES) {
            float s = g_inv[grow];
            const float* src = sC + r * C2_LD + hh * 20;
            uint2* dst = (uint2*)((__half*)g_h2ph + (size_t)grow * FOUT + hh * 20);
#pragma unroll
            for (int b = 0; b < 5; b++) {
                __half2 h0 = __floats2half2_rn(src[b * 4 + 0] * s, src[b * 4 + 1] * s);
                __half2 h1 = __floats2half2_rn(src[b * 4 + 2] * s, src[b * 4 + 3] * s);
                dst[b] = make_uint2(*(uint32_t*)&h0, *(uint32_t*)&h1);
            }
        }
    }
}

// gather-aggregate layer2: out[d] = inv[d]*(sum + self) + b2; 8-wide batching
__global__ void __launch_bounds__(320) k_agg2(const float* __restrict__ b2,
                                              float* __restrict__ out) {
    long long t = (long long)blockIdx.x * 320 + threadIdx.x;
    int d = (int)(t / 10);
    if (d >= N_NODES) return;
    int q = (int)(t - (long long)d * 10);
    int cnt = g_deg[d];
    if (cnt > MAXD) cnt = MAXD;
    const int* sp = g_srcs + (size_t)d * MAXD;

    float4 acc = h4_to_f4(((const uint2*)(g_h2ph + (size_t)d * 20))[q]);   // self (already *inv)

    int j = 0;
    for (; j + 8 <= cnt; j += 8) {
        int   si[8];
        uint2 ri[8];
#pragma unroll
        for (int u = 0; u < 8; u++) si[u] = __ldg(&sp[j + u]);
#pragma unroll
        for (int u = 0; u < 8; u++)
            ri[u] = __ldg((const uint2*)(g_h2ph + (size_t)si[u] * 20) + q);
#pragma unroll
        for (int u = 0; u < 8; u++) {
            float4 v = h4_to_f4(ri[u]);
            acc.x += v.x; acc.y += v.y; acc.z += v.z; acc.w += v.w;
        }
    }
    for (; j < cnt; j++) {
        int s = __ldg(&sp[j]);
        float4 v = h4_to_f4(__ldg((const uint2*)(g_h2ph + (size_t)s * 20) + q));
        acc.x += v.x; acc.y += v.y; acc.z += v.z; acc.w += v.w;
    }

    float w = g_inv[d];
    float4 bv = ((const float4*)b2)[q];
    ((float4*)out)[(size_t)d * 10 + q] =
        make_float4(acc.x * w + bv.x, acc.y * w + bv.y,
                    acc.z * w + bv.z, acc.w * w + bv.w);
}

// ---------------- launch ----------------
extern "C" void kernel_launch(void* const* d_in, const int* in_sizes, int n_in,
                              void* d_out, int out_size) {
    const float* x  = (const float*)d_in[0];
    const void*  ei = d_in[1];
    const float* W1 = (const float*)d_in[2];
    const float* b1 = (const float*)d_in[3];
    const float* W2 = (const float*)d_in[4];
    const float* b2 = (const float*)d_in[5];
    float* out = (float*)d_out;

    k_init<<<(N_NODES + 255) / 256, 256>>>((const long long*)ei, W1);
    k_fused<<<GEMM1_BLOCKS + BUCKET_BLOCKS, 256>>>(x, ei);
    k_inv<<<(N_NODES + 255) / 256, 256>>>();
    k_agg1<<<(int)(((long long)N_NODES * 16 + 255) / 256), 256>>>(b1);
    k_gemm2<<<(N_NODES + 127) / 128, 256>>>(W2);
    k_agg2<<<(int)(((long long)N_NODES * 10 + 319) / 320), 320>>>(b2, out);
}